// round 1
// baseline (speedup 1.0000x reference)
#include <cuda_runtime.h>
#include <cuda_bf16.h>

#define D 128
#define NNBR 32
#define NB_PITCH 129          // padded row pitch (floats) -> conflict-free lane-per-row LDS
#define THREADS 128
#define LRELU 0.2f

__device__ __forceinline__ unsigned long long ffma2(unsigned long long a,
                                                    unsigned long long b,
                                                    unsigned long long c) {
    unsigned long long d;
    asm("fma.rn.f32x2 %0, %1, %2, %3;" : "=l"(d) : "l"(a), "l"(b), "l"(c));
    return d;
}

__device__ __forceinline__ unsigned long long pack2(float x) {
    unsigned long long r;
    unsigned u = __float_as_uint(x);
    asm("mov.b64 %0, {%1, %2};" : "=l"(r) : "r"(u), "r"(u));
    return r;
}

// SMEM layout (floats):
//   w_s    : [0, 16384)            w[k][e] row-major (matches global)
//   nb_s   : [16384, +32*129)      neighbor tile, padded pitch; reused as reduce scratch
//   self_s : [.., +128)
//   q_s    : [.., +128)
//   sc_s   : [.., +128)            per-warp score partials [4][32]
#define SMEM_FLOATS (16384 + NNBR * NB_PITCH + 128 + 128 + 128)

__global__ void __launch_bounds__(THREADS)
hete_agg_kernel(const float* __restrict__ self_v,
                const float* __restrict__ nb_g,
                const float* __restrict__ w_g,
                const float* __restrict__ q_g,
                float* __restrict__ out,
                int B) {
    extern __shared__ float sm[];
    float* w_s    = sm;
    float* nb_s   = sm + 16384;
    float* self_s = nb_s + NNBR * NB_PITCH;
    float* q_s    = self_s + 128;
    float* sc_s   = q_s + 128;

    const int tid  = threadIdx.x;
    const int lane = tid & 31;
    const int wid  = tid >> 5;
    const int c0   = wid << 5;   // this warp's column block base

    // Stage w (64KB) once per CTA, vectorized. q once.
    {
        const float4* wg4 = reinterpret_cast<const float4*>(w_g);
        float4* ws4 = reinterpret_cast<float4*>(w_s);
        #pragma unroll 4
        for (int i = tid; i < (D * D) / 4; i += THREADS) ws4[i] = wg4[i];
        q_s[tid] = q_g[tid];
    }
    // (first __syncthreads inside the batch loop covers visibility)

    for (int b = blockIdx.x; b < B; b += gridDim.x) {
        // ---- stage neighbor tile (padded pitch) + self vector ----
        const float* nbp = nb_g + (size_t)b * (NNBR * D);
        #pragma unroll 4
        for (int i = tid; i < NNBR * D; i += THREADS) {
            nb_s[(i >> 7) * NB_PITCH + (i & 127)] = nbp[i];
        }
        self_s[tid] = self_v[(size_t)b * D + tid];
        __syncthreads();

        // ---- mainloop: msg[lane][c0..c0+31] = sum_k nb[lane][k] * w[k][c] ----
        unsigned long long acc[16];
        #pragma unroll
        for (int j = 0; j < 16; j++) acc[j] = 0ull;

        const float* nbrow = nb_s + lane * NB_PITCH;
        #pragma unroll 4
        for (int k = 0; k < D; k++) {
            const unsigned long long nb2 = pack2(nbrow[k]);
            const ulonglong2* wr =
                reinterpret_cast<const ulonglong2*>(w_s + k * D + c0);
            #pragma unroll
            for (int j = 0; j < 8; j++) {
                ulonglong2 wv = wr[j];
                acc[2 * j]     = ffma2(nb2, wv.x, acc[2 * j]);
                acc[2 * j + 1] = ffma2(nb2, wv.y, acc[2 * j + 1]);
            }
        }
        const float* af = reinterpret_cast<const float*>(acc); // af[t] = msg[lane][c0+t]

        // ---- attention score partial: leaky(self*msg) . q over this warp's cols ----
        float s = 0.f;
        #pragma unroll
        for (int t = 0; t < 32; t++) {
            float x = self_s[c0 + t] * af[t];
            x = (x >= 0.f) ? x : LRELU * x;
            s = fmaf(x, q_s[c0 + t], s);
        }
        sc_s[wid * 32 + lane] = s;
        __syncthreads();

        // ---- full score + warp softmax over 32 neighbors (lane = neighbor) ----
        float score = sc_s[lane] + sc_s[32 + lane] + sc_s[64 + lane] + sc_s[96 + lane];
        float mx = score;
        #pragma unroll
        for (int o = 16; o; o >>= 1) mx = fmaxf(mx, __shfl_xor_sync(0xffffffffu, mx, o));
        float e = expf(score - mx);
        float ssum = e;
        #pragma unroll
        for (int o = 16; o; o >>= 1) ssum += __shfl_xor_sync(0xffffffffu, ssum, o);
        const float al = e / ssum;

        // ---- out[c] = sum_n alpha_n * msg[n][c]; reduce via reused nb_s scratch ----
        float* red = nb_s;  // safe: all mainloop reads of nb_s done before last sync
        #pragma unroll
        for (int t = 0; t < 32; t++) red[lane * NB_PITCH + c0 + t] = al * af[t];
        __syncthreads();

        float o = 0.f;
        #pragma unroll
        for (int l = 0; l < 32; l++) o += red[l * NB_PITCH + tid];
        out[(size_t)b * D + tid] = o;
        __syncthreads();  // protect scratch/self_s before next batch's staging
    }
}

extern "C" void kernel_launch(void* const* d_in, const int* in_sizes, int n_in,
                              void* d_out, int out_size) {
    const float* self_v = (const float*)d_in[0];   // [B, 128]
    const float* nb_g   = (const float*)d_in[1];   // [B, 32, 128]
    const float* w_g    = (const float*)d_in[2];   // [128, 128]
    const float* q_g    = (const float*)d_in[3];   // [128, 1]
    float* out = (float*)d_out;

    const int B = in_sizes[0] / D;

    const size_t smem_bytes = SMEM_FLOATS * sizeof(float);  // ~83.6 KB
    cudaFuncSetAttribute(hete_agg_kernel,
                         cudaFuncAttributeMaxDynamicSharedMemorySize,
                         (int)smem_bytes);

    int dev = 0, nsm = 148;
    cudaGetDevice(&dev);
    cudaDeviceGetAttribute(&nsm, cudaDevAttrMultiProcessorCount, dev);
    int grid = 2 * nsm;            // persistent: 2 CTAs/SM (smem-limited)
    if (grid > B) grid = B;

    hete_agg_kernel<<<grid, THREADS, smem_bytes>>>(self_v, nb_g, w_g, q_g, out, B);
}

// round 3
// speedup vs baseline: 1.9778x; 1.9778x over previous
#include <cuda_runtime.h>
#include <cuda_fp16.h>
#include <cstdint>

#define THREADS 128
#define DDIM    128
#define NNBR    32
#define GB      4                  // batches per group -> M = 128 rows
#define LRELU   0.2f

#define PITCH_B   272              // bytes per row of fp16 tiles (17 * 16B -> LDSM conflict-free)
#define MSG_PITCH 136              // floats per msg row

// ---------------- SMEM layout (bytes) ----------------
#define SM_W_HI   0                            // w^T hi  [e][k] fp16, 128 x 272B
#define SM_W_LO   (SM_W_HI + 128 * PITCH_B)    // 34816
#define SM_NB_HI  (SM_W_LO + 128 * PITCH_B)    // 69632
#define SM_NB_LO  (SM_NB_HI + 128 * PITCH_B)   // nb hi/lo [row][k] fp16
#define SM_MSG    SM_NB_HI                     // msg fp32 128 x 136 (69632B) overlays nb after GEMM
#define SM_SELF   (SM_NB_LO + 128 * PITCH_B)   // 4 x 128 fp32
#define SM_Q      (SM_SELF + 2048)             // 128 fp32
#define SM_SC     (SM_Q + 512)                 // 128 x 33 fp32
#define SM_PART   (SM_SC + 16896)              // 4 x 32 fp32
#define SM_TOTAL  (SM_PART + 512)              // ~156 KB

__device__ __forceinline__ uint32_t smem_u32(const void* p) {
    uint32_t a;
    asm("{ .reg .u64 t; cvta.to.shared.u64 t, %1; cvt.u32.u64 %0, t; }" : "=r"(a) : "l"(p));
    return a;
}

__device__ __forceinline__ void ldsm_x4(uint32_t* r, uint32_t addr) {
    asm volatile("ldmatrix.sync.aligned.m8n8.x4.shared.b16 {%0,%1,%2,%3}, [%4];"
                 : "=r"(r[0]), "=r"(r[1]), "=r"(r[2]), "=r"(r[3]) : "r"(addr));
}
__device__ __forceinline__ void ldsm_x2(uint32_t* r, uint32_t addr) {
    asm volatile("ldmatrix.sync.aligned.m8n8.x2.shared.b16 {%0,%1}, [%2];"
                 : "=r"(r[0]), "=r"(r[1]) : "r"(addr));
}
__device__ __forceinline__ void mma16816(float* d, const uint32_t* a, const uint32_t* b) {
    asm volatile("mma.sync.aligned.m16n8k16.row.col.f32.f16.f16.f32 "
                 "{%0,%1,%2,%3}, {%4,%5,%6,%7}, {%8,%9}, {%0,%1,%2,%3};"
                 : "+f"(d[0]), "+f"(d[1]), "+f"(d[2]), "+f"(d[3])
                 : "r"(a[0]), "r"(a[1]), "r"(a[2]), "r"(a[3]), "r"(b[0]), "r"(b[1]));
}

__global__ void __launch_bounds__(THREADS, 1)
hete_agg_hmma(const float* __restrict__ self_v,
              const float* __restrict__ nb_g,
              const float* __restrict__ w_g,
              const float* __restrict__ q_g,
              float* __restrict__ out,
              int B) {
    extern __shared__ char smem[];
    const uint32_t smb = smem_u32(smem);
    const int tid  = threadIdx.x;
    const int lane = tid & 31;
    const int wid  = tid >> 5;
    const int mbase = (wid >> 1) * 64;         // warp quadrant
    const int nbase = (wid & 1) * 64;

    float* self_s = reinterpret_cast<float*>(smem + SM_SELF);
    float* q_s    = reinterpret_cast<float*>(smem + SM_Q);
    float* sc_s   = reinterpret_cast<float*>(smem + SM_SC);
    float* part_s = reinterpret_cast<float*>(smem + SM_PART);
    float* msg_s  = reinterpret_cast<float*>(smem + SM_MSG);

    // ---- stage w^T hi/lo fp16 (once per CTA); reads coalesced over e ----
    for (int idx = tid; idx < DDIM * DDIM; idx += THREADS) {
        int k = idx >> 7, e = idx & 127;
        float x = w_g[idx];
        __half h = __float2half_rn(x);
        __half l = __float2half_rn(x - __half2float(h));
        *reinterpret_cast<__half*>(smem + SM_W_HI + e * PITCH_B + k * 2) = h;
        *reinterpret_cast<__half*>(smem + SM_W_LO + e * PITCH_B + k * 2) = l;
    }
    if (tid < DDIM) q_s[tid] = q_g[tid];

    const int ngroups = (B + GB - 1) / GB;

    for (int grp = blockIdx.x; grp < ngroups; grp += gridDim.x) {
        const int b0 = grp * GB;

        // ---- stage nb hi/lo fp16: row = g*32 + n, 128 rows; 1 row/warp/iter ----
        #pragma unroll 4
        for (int i = 0; i < 32; i++) {
            int row = i * 4 + wid;
            int b   = b0 + (row >> 5);
            int bc  = (b < B) ? b : (B - 1);
            const float4 v = *reinterpret_cast<const float4*>(
                nb_g + ((size_t)bc * NNBR + (row & 31)) * DDIM + lane * 4);
            __half h0 = __float2half_rn(v.x), h1 = __float2half_rn(v.y);
            __half h2 = __float2half_rn(v.z), h3 = __float2half_rn(v.w);
            __half l0 = __float2half_rn(v.x - __half2float(h0));
            __half l1 = __float2half_rn(v.y - __half2float(h1));
            __half l2 = __float2half_rn(v.z - __half2float(h2));
            __half l3 = __float2half_rn(v.w - __half2float(h3));
            uint2 hv, lv;
            hv.x = ((uint32_t)__half_as_ushort(h1) << 16) | __half_as_ushort(h0);
            hv.y = ((uint32_t)__half_as_ushort(h3) << 16) | __half_as_ushort(h2);
            lv.x = ((uint32_t)__half_as_ushort(l1) << 16) | __half_as_ushort(l0);
            lv.y = ((uint32_t)__half_as_ushort(l3) << 16) | __half_as_ushort(l2);
            uint32_t off = row * PITCH_B + lane * 8;
            *reinterpret_cast<uint2*>(smem + SM_NB_HI + off) = hv;
            *reinterpret_cast<uint2*>(smem + SM_NB_LO + off) = lv;
        }
        #pragma unroll
        for (int i = 0; i < GB; i++) {
            int b = b0 + i;
            int bc = (b < B) ? b : (B - 1);
            self_s[i * DDIM + tid] = self_v[(size_t)bc * DDIM + tid];
        }
        __syncthreads();

        // ---- GEMM: msg = nb @ w^T^T  via 3 compensated passes ----
        float acc[4][8][4];
        #pragma unroll
        for (int mt = 0; mt < 4; mt++)
            #pragma unroll
            for (int nt = 0; nt < 8; nt++)
                #pragma unroll
                for (int j = 0; j < 4; j++) acc[mt][nt][j] = 0.f;

        #pragma unroll 1
        for (int p = 0; p < 3; p++) {
            const uint32_t Ab = smb + ((p == 2) ? SM_NB_LO : SM_NB_HI);
            const uint32_t Bb = smb + ((p == 1) ? SM_W_LO : SM_W_HI);
            // per-lane ldmatrix row addresses
            const uint32_t a_base = Ab + (mbase + (lane & 15)) * PITCH_B + ((lane >> 4) << 4);
            const uint32_t b_base = Bb + (nbase + (lane & 7)) * PITCH_B + ((lane & 8) ? 16 : 0);
            #pragma unroll
            for (int ks = 0; ks < 8; ks++) {
                const uint32_t ka = ks * 32;
                uint32_t Ar[4][4];
                #pragma unroll
                for (int mt = 0; mt < 4; mt++)
                    ldsm_x4(Ar[mt], a_base + mt * 16 * PITCH_B + ka);
                #pragma unroll
                for (int nt = 0; nt < 8; nt++) {
                    uint32_t Br[2];
                    ldsm_x2(Br, b_base + nt * 8 * PITCH_B + ka);
                    #pragma unroll
                    for (int mt = 0; mt < 4; mt++)
                        mma16816(acc[mt][nt], Ar[mt], Br);
                }
            }
        }
        __syncthreads();   // all HMMA reads of nb done before msg overlay

        // ---- spill msg quadrant to SMEM: msg[row][e] fp32, pitch 136 ----
        {
            const int r0 = mbase + (lane >> 2);
            const int c0 = nbase + 2 * (lane & 3);
            #pragma unroll
            for (int mt = 0; mt < 4; mt++)
                #pragma unroll
                for (int nt = 0; nt < 8; nt++) {
                    float* d = acc[mt][nt];
                    const int r = r0 + mt * 16;
                    const int c = c0 + nt * 8;
                    *reinterpret_cast<float2*>(msg_s + r * MSG_PITCH + c) =
                        make_float2(d[0], d[1]);
                    *reinterpret_cast<float2*>(msg_s + (r + 8) * MSG_PITCH + c) =
                        make_float2(d[2], d[3]);
                }
        }
        __syncthreads();

        // ---- epilogue per batch g ----
        const int e = tid;
        const float qe = q_s[e];
        #pragma unroll 1
        for (int g = 0; g < GB; g++) {
            float mcol[32];
            const float* mrow = msg_s + (g * 32) * MSG_PITCH + e;
            #pragma unroll
            for (int n = 0; n < 32; n++) mcol[n] = mrow[n * MSG_PITCH];

            const float sv = self_s[g * DDIM + e];
            float* my_sc = sc_s + e * 33;
            #pragma unroll
            for (int n = 0; n < 32; n++) {
                float x = sv * mcol[n];
                x = (x >= 0.f) ? x : LRELU * x;
                my_sc[n] = x * qe;
            }
            __syncthreads();

            {   // transpose-reduce: thread (qq,n) sums 32 e-rows
                const int n = tid & 31, qq = tid >> 5;
                const float* col = sc_s + (qq * 32) * 33 + n;
                float s = 0.f;
                #pragma unroll
                for (int i = 0; i < 32; i++) s += col[i * 33];
                part_s[qq * 32 + n] = s;
            }
            __syncthreads();

            float score = part_s[lane] + part_s[32 + lane] + part_s[64 + lane] + part_s[96 + lane];
            float mx = score;
            #pragma unroll
            for (int o = 16; o; o >>= 1) mx = fmaxf(mx, __shfl_xor_sync(0xffffffffu, mx, o));
            float ex = expf(score - mx);
            float ssum = ex;
            #pragma unroll
            for (int o = 16; o; o >>= 1) ssum += __shfl_xor_sync(0xffffffffu, ssum, o);
            const float alpha = ex / ssum;

            float o = 0.f;
            #pragma unroll
            for (int n = 0; n < 32; n++)
                o = fmaf(__shfl_sync(0xffffffffu, alpha, n), mcol[n], o);

            const int b = b0 + g;
            if (b < B) out[(size_t)b * DDIM + e] = o;
            __syncthreads();
        }
        __syncthreads();   // msg region free -> next group's nb staging
    }
}

extern "C" void kernel_launch(void* const* d_in, const int* in_sizes, int n_in,
                              void* d_out, int out_size) {
    const float* self_v = (const float*)d_in[0];   // [B, 128]
    const float* nb_g   = (const float*)d_in[1];   // [B, 32, 128]
    const float* w_g    = (const float*)d_in[2];   // [128, 128]
    const float* q_g    = (const float*)d_in[3];   // [128, 1]
    float* out = (float*)d_out;

    const int B = in_sizes[0] / DDIM;
    const int ngroups = (B + GB - 1) / GB;

    cudaFuncSetAttribute(hete_agg_hmma, cudaFuncAttributeMaxDynamicSharedMemorySize, SM_TOTAL);

    int dev = 0, nsm = 148;
    cudaGetDevice(&dev);
    cudaDeviceGetAttribute(&nsm, cudaDevAttrMultiProcessorCount, dev);
    int grid = (ngroups < nsm) ? ngroups : nsm;

    hete_agg_hmma<<<grid, THREADS, SM_TOTAL>>>(self_v, nb_g, w_g, q_g, out, B);
}

// round 5
// speedup vs baseline: 2.8851x; 1.4588x over previous
#include <cuda_runtime.h>
#include <cuda_fp16.h>
#include <cstdint>

#define THREADS 256
#define DDIM    128
#define NNBR    32
#define GB      4                 // batches per group -> 128 GEMM rows
#define LRELU   0.2f

#define PITCH_B   272             // bytes/row of fp16 tiles (17*16B -> ldsm conflict-free)
#define MSG_PITCH 136             // floats/row of msg

// ---------------- SMEM layout (bytes) ----------------
#define SM_W_HI   0
#define SM_W_LO   (SM_W_HI  + 128 * PITCH_B)     // 34816
#define SM_NB_HI  (SM_W_LO  + 128 * PITCH_B)     // 69632
#define SM_NB_LO  (SM_NB_HI + 128 * PITCH_B)     // 104448
#define SM_MSG    (SM_NB_LO + 128 * PITCH_B)     // 139264 (msg fp32 128 x 136)
#define SM_SELF   (SM_MSG   + 128 * MSG_PITCH * 4)  // 208896: self [2 buf][4][128] fp32
#define SM_Q      (SM_SELF  + 2 * GB * DDIM * 4)    // 212992
#define SM_SCORE  (SM_Q     + 512)                  // 213504: scores [2 gi][2 half][32]
#define SM_TOTAL  (SM_SCORE + 512)                  // 214016 B (~209 KB)

__device__ __forceinline__ uint32_t smem_u32(const void* p) {
    uint32_t a;
    asm("{ .reg .u64 t; cvta.to.shared.u64 t, %1; cvt.u32.u64 %0, t; }" : "=r"(a) : "l"(p));
    return a;
}
__device__ __forceinline__ void ldsm_x4(uint32_t* r, uint32_t addr) {
    asm volatile("ldmatrix.sync.aligned.m8n8.x4.shared.b16 {%0,%1,%2,%3}, [%4];"
                 : "=r"(r[0]), "=r"(r[1]), "=r"(r[2]), "=r"(r[3]) : "r"(addr));
}
__device__ __forceinline__ void mma16816(float* d, const uint32_t* a, const uint32_t* b) {
    asm volatile("mma.sync.aligned.m16n8k16.row.col.f32.f16.f16.f32 "
                 "{%0,%1,%2,%3}, {%4,%5,%6,%7}, {%8,%9}, {%0,%1,%2,%3};"
                 : "+f"(d[0]), "+f"(d[1]), "+f"(d[2]), "+f"(d[3])
                 : "r"(a[0]), "r"(a[1]), "r"(a[2]), "r"(a[3]), "r"(b[0]), "r"(b[1]));
}

// convert one float4 (4 consecutive k-values, 8 bytes of fp16) and store hi/lo
__device__ __forceinline__ void cvt_store_nb(char* smem, int row, int c4, float4 v) {
    __half h0 = __float2half_rn(v.x), h1 = __float2half_rn(v.y);
    __half h2 = __float2half_rn(v.z), h3 = __float2half_rn(v.w);
    __half l0 = __float2half_rn(v.x - __half2float(h0));
    __half l1 = __float2half_rn(v.y - __half2float(h1));
    __half l2 = __float2half_rn(v.z - __half2float(h2));
    __half l3 = __float2half_rn(v.w - __half2float(h3));
    uint2 hv, lv;
    hv.x = ((uint32_t)__half_as_ushort(h1) << 16) | __half_as_ushort(h0);
    hv.y = ((uint32_t)__half_as_ushort(h3) << 16) | __half_as_ushort(h2);
    lv.x = ((uint32_t)__half_as_ushort(l1) << 16) | __half_as_ushort(l0);
    lv.y = ((uint32_t)__half_as_ushort(l3) << 16) | __half_as_ushort(l2);
    uint32_t off = (uint32_t)row * PITCH_B + (uint32_t)c4 * 8;   // 4 fp16 = 8 bytes (R4 bug: *16)
    *reinterpret_cast<uint2*>(smem + SM_NB_HI + off) = hv;
    *reinterpret_cast<uint2*>(smem + SM_NB_LO + off) = lv;
}

__global__ void __launch_bounds__(THREADS, 1)
hete_agg_hmma2(const float* __restrict__ self_v,
               const float* __restrict__ nb_g,
               const float* __restrict__ w_g,
               const float* __restrict__ q_g,
               float* __restrict__ out,
               int B) {
    extern __shared__ char smem[];
    const uint32_t smb = smem_u32(smem);
    const int tid  = threadIdx.x;
    const int lane = tid & 31;
    const int wid  = tid >> 5;
    const int mbase = (wid >> 1) * 32;     // warp tile: rows [mbase,+32)
    const int nbase = (wid & 1) * 64;      //            cols [nbase,+64)

    float* self_s  = reinterpret_cast<float*>(smem + SM_SELF);
    float* q_s     = reinterpret_cast<float*>(smem + SM_Q);
    float* msg_s   = reinterpret_cast<float*>(smem + SM_MSG);
    float* score_s = reinterpret_cast<float*>(smem + SM_SCORE);

    // ---- stage w^T hi/lo fp16 (once); q ----
    for (int idx = tid; idx < DDIM * DDIM; idx += THREADS) {
        int k = idx >> 7, e = idx & 127;
        float x = w_g[idx];
        __half h = __float2half_rn(x);
        __half l = __float2half_rn(x - __half2float(h));
        *reinterpret_cast<__half*>(smem + SM_W_HI + e * PITCH_B + k * 2) = h;
        *reinterpret_cast<__half*>(smem + SM_W_LO + e * PITCH_B + k * 2) = l;
    }
    if (tid < DDIM) q_s[tid] = q_g[tid];

    const int ngroups = (B + GB - 1) / GB;

    // ---- prologue: stage nb + self for first group (buf 0) ----
    int grp = blockIdx.x;
    if (grp < ngroups) {
        const int b0 = grp * GB;
        #pragma unroll
        for (int it = 0; it < 16; it++) {
            int unit = it * 256 + tid;          // float4 index in 128x32
            int row = unit >> 5;
            int b = b0 + (row >> 5);
            int bc = (b < B) ? b : (B - 1);
            float4 v = *reinterpret_cast<const float4*>(
                nb_g + ((size_t)bc * NNBR + (row & 31)) * DDIM + (unit & 31) * 4);
            cvt_store_nb(smem, row, unit & 31, v);
        }
        #pragma unroll
        for (int j = 0; j < 2; j++) {
            int u = j * 256 + tid;
            int b = b0 + (u >> 7);
            int bc = (b < B) ? b : (B - 1);
            self_s[u] = self_v[(size_t)bc * DDIM + (u & 127)];
        }
    }

    int buf = 0;
    for (; grp < ngroups; grp += gridDim.x) {
        const int b0 = grp * GB;
        __syncthreads();                       // staged nb/self visible

        // ================= GEMM: fused 3-pass compensated =================
        float acc[2][8][4];
        #pragma unroll
        for (int mt = 0; mt < 2; mt++)
            #pragma unroll
            for (int nt = 0; nt < 8; nt++)
                #pragma unroll
                for (int j = 0; j < 4; j++) acc[mt][nt][j] = 0.f;

        const uint32_t a_off = (uint32_t)(mbase + (lane & 15)) * PITCH_B + ((lane >> 4) << 4);
        const uint32_t a_hi = smb + SM_NB_HI + a_off;
        const uint32_t a_lo = smb + SM_NB_LO + a_off;
        // pair-load B: lanes 0-7: rows n0-7/k0-7; 8-15: n0-7/k8-15; 16-23: n8-15/k0-7; 24-31: n8-15/k8-15
        const uint32_t b_off = (uint32_t)(nbase + ((lane >> 4) << 3) + (lane & 7)) * PITCH_B
                               + (((lane >> 3) & 1) << 4);
        const uint32_t b_hi = smb + SM_W_HI + b_off;
        const uint32_t b_lo = smb + SM_W_LO + b_off;

        #pragma unroll 1
        for (int ks = 0; ks < 8; ks++) {
            const uint32_t ka = ks * 32;
            uint32_t Ah[2][4], Al[2][4];
            ldsm_x4(Ah[0], a_hi + ka);
            ldsm_x4(Ah[1], a_hi + 16 * PITCH_B + ka);
            ldsm_x4(Al[0], a_lo + ka);
            ldsm_x4(Al[1], a_lo + 16 * PITCH_B + ka);
            uint32_t Bh[4][4], Bl[4][4];       // pair p covers nt 2p, 2p+1
            #pragma unroll
            for (int p = 0; p < 4; p++) {
                ldsm_x4(Bh[p], b_hi + p * 16 * PITCH_B + ka);
                ldsm_x4(Bl[p], b_lo + p * 16 * PITCH_B + ka);
            }
            // pass 1: Ah*Bh
            #pragma unroll
            for (int p = 0; p < 4; p++)
                #pragma unroll
                for (int hf = 0; hf < 2; hf++)
                    #pragma unroll
                    for (int mt = 0; mt < 2; mt++)
                        mma16816(acc[mt][2 * p + hf], Ah[mt], &Bh[p][2 * hf]);
            // pass 2: Ah*Bl
            #pragma unroll
            for (int p = 0; p < 4; p++)
                #pragma unroll
                for (int hf = 0; hf < 2; hf++)
                    #pragma unroll
                    for (int mt = 0; mt < 2; mt++)
                        mma16816(acc[mt][2 * p + hf], Ah[mt], &Bl[p][2 * hf]);
            // pass 3: Al*Bh
            #pragma unroll
            for (int p = 0; p < 4; p++)
                #pragma unroll
                for (int hf = 0; hf < 2; hf++)
                    #pragma unroll
                    for (int mt = 0; mt < 2; mt++)
                        mma16816(acc[mt][2 * p + hf], Al[mt], &Bh[p][2 * hf]);
        }

        // ---- spill msg quadrant: msg[row][e] fp32 pitch 136 ----
        {
            const int r0 = mbase + (lane >> 2);
            const int c0 = nbase + 2 * (lane & 3);
            #pragma unroll
            for (int mt = 0; mt < 2; mt++)
                #pragma unroll
                for (int nt = 0; nt < 8; nt++) {
                    const float* d = acc[mt][nt];
                    const int r = r0 + mt * 16;
                    const int c = c0 + nt * 8;
                    *reinterpret_cast<float2*>(msg_s + r * MSG_PITCH + c) =
                        make_float2(d[0], d[1]);
                    *reinterpret_cast<float2*>(msg_s + (r + 8) * MSG_PITCH + c) =
                        make_float2(d[2], d[3]);
                }
        }
        __syncthreads();                       // msg visible; nb buffers free

        // ---- prefetch next group's raw nb/self into registers ----
        const int ngrp = grp + gridDim.x;
        const bool hasnext = (ngrp < ngroups);
        float4 raw[16];
        float selfraw[2];
        if (hasnext) {
            const int b0n = ngrp * GB;
            #pragma unroll
            for (int it = 0; it < 16; it++) {
                int unit = it * 256 + tid;
                int row = unit >> 5;
                int b = b0n + (row >> 5);
                int bc = (b < B) ? b : (B - 1);
                raw[it] = *reinterpret_cast<const float4*>(
                    nb_g + ((size_t)bc * NNBR + (row & 31)) * DDIM + (unit & 31) * 4);
            }
            #pragma unroll
            for (int j = 0; j < 2; j++) {
                int u = j * 256 + tid;
                int b = b0n + (u >> 7);
                int bc = (b < B) ? b : (B - 1);
                selfraw[j] = self_v[(size_t)bc * DDIM + (u & 127)];
            }
        }

        // ================= epilogue (overlaps the LDGs above) =================
        const int half  = tid >> 7;            // 0/1: which batch of the pair
        const int htid  = tid & 127;
        const int hw    = (tid >> 5) & 3;      // warp within half
        const float* selfb = self_s + buf * (GB * DDIM);

        #pragma unroll 1
        for (int gi = 0; gi < 2; gi++) {
            const int g = gi * 2 + half;
            // preload per-lane self/q for e = lane + 32c
            float sv[4], qv[4];
            #pragma unroll
            for (int c = 0; c < 4; c++) {
                sv[c] = selfb[g * DDIM + lane + 32 * c];
                qv[c] = q_s[lane + 32 * c];
            }
            // scores for neighbors n = hw*8 .. +7 (warp-reduce over e)
            #pragma unroll
            for (int j = 0; j < 8; j++) {
                const int n = hw * 8 + j;
                const float* mrow = msg_s + (g * 32 + n) * MSG_PITCH;
                float s = 0.f;
                #pragma unroll
                for (int c = 0; c < 4; c++) {
                    float x = sv[c] * mrow[lane + 32 * c];
                    x = (x >= 0.f) ? x : LRELU * x;
                    s = fmaf(x, qv[c], s);
                }
                #pragma unroll
                for (int o = 16; o; o >>= 1) s += __shfl_xor_sync(0xffffffffu, s, o);
                if (lane == 0) score_s[gi * 64 + half * 32 + n] = s;
            }
            __syncthreads();

            // softmax over 32 neighbors (lane = n), redundant per warp
            float sc = score_s[gi * 64 + half * 32 + lane];
            float mx = sc;
            #pragma unroll
            for (int o = 16; o; o >>= 1) mx = fmaxf(mx, __shfl_xor_sync(0xffffffffu, mx, o));
            float ex = expf(sc - mx);
            float ssum = ex;
            #pragma unroll
            for (int o = 16; o; o >>= 1) ssum += __shfl_xor_sync(0xffffffffu, ssum, o);
            const float alpha = ex / ssum;

            // out[e] = sum_n alpha_n * msg[n][e]
            const int e = htid;
            float o = 0.f;
            #pragma unroll
            for (int n = 0; n < 32; n++) {
                float a = __shfl_sync(0xffffffffu, alpha, n);
                o = fmaf(a, msg_s[(g * 32 + n) * MSG_PITCH + e], o);
            }
            const int b = b0 + g;
            if (b < B) out[(size_t)b * DDIM + e] = o;
        }

        // ---- commit prefetched nb/self for next group ----
        if (hasnext) {
            #pragma unroll
            for (int it = 0; it < 16; it++) {
                int unit = it * 256 + tid;
                cvt_store_nb(smem, unit >> 5, unit & 31, raw[it]);
            }
            float* selfn = self_s + (buf ^ 1) * (GB * DDIM);
            #pragma unroll
            for (int j = 0; j < 2; j++) selfn[j * 256 + tid] = selfraw[j];
        }
        buf ^= 1;
    }
}

extern "C" void kernel_launch(void* const* d_in, const int* in_sizes, int n_in,
                              void* d_out, int out_size) {
    const float* self_v = (const float*)d_in[0];   // [B, 128]
    const float* nb_g   = (const float*)d_in[1];   // [B, 32, 128]
    const float* w_g    = (const float*)d_in[2];   // [128, 128]
    const float* q_g    = (const float*)d_in[3];   // [128, 1]
    float* out = (float*)d_out;

    const int B = in_sizes[0] / DDIM;
    const int ngroups = (B + GB - 1) / GB;

    cudaFuncSetAttribute(hete_agg_hmma2, cudaFuncAttributeMaxDynamicSharedMemorySize, SM_TOTAL);

    int dev = 0, nsm = 148;
    cudaGetDevice(&dev);
    cudaDeviceGetAttribute(&nsm, cudaDevAttrMultiProcessorCount, dev);
    int grid = (ngroups < nsm) ? ngroups : nsm;

    hete_agg_hmma2<<<grid, THREADS, SM_TOTAL>>>(self_v, nb_g, w_g, q_g, out, B);
}

// round 6
// speedup vs baseline: 3.5410x; 1.2273x over previous
#include <cuda_runtime.h>
#include <cuda_fp16.h>
#include <cstdint>

#define THREADS 512
#define DDIM    128
#define NNBR    32
#define GB      4                 // batches per group -> 128 GEMM rows
#define LRELU   0.2f

#define PITCH_B   272             // bytes/row of fp16 tiles (17*16B -> ldsm conflict-free)
#define MSG_PITCH 136             // floats/row of msg

// ---------------- SMEM layout (bytes) ----------------
#define SM_W_HI   0
#define SM_W_LO   (SM_W_HI  + 128 * PITCH_B)     // 34816
#define SM_NB_HI  (SM_W_LO  + 128 * PITCH_B)     // 69632
#define SM_NB_LO  (SM_NB_HI + 128 * PITCH_B)     // 104448
#define SM_MSG    (SM_NB_LO + 128 * PITCH_B)     // 139264 (msg fp32 128 x 136)
#define SM_SELF   (SM_MSG   + 128 * MSG_PITCH * 4)  // 208896: self [2 buf][4][128] fp32
#define SM_Q      (SM_SELF  + 2 * GB * DDIM * 4)    // 212992
#define SM_SCORE  (SM_Q     + 512)                  // 213504: scores [4 g][32]
#define SM_TOTAL  (SM_SCORE + 512)                  // 214016 B (~209 KB)

__device__ __forceinline__ uint32_t smem_u32(const void* p) {
    uint32_t a;
    asm("{ .reg .u64 t; cvta.to.shared.u64 t, %1; cvt.u32.u64 %0, t; }" : "=r"(a) : "l"(p));
    return a;
}
__device__ __forceinline__ void ldsm_x4(uint32_t* r, uint32_t addr) {
    asm volatile("ldmatrix.sync.aligned.m8n8.x4.shared.b16 {%0,%1,%2,%3}, [%4];"
                 : "=r"(r[0]), "=r"(r[1]), "=r"(r[2]), "=r"(r[3]) : "r"(addr));
}
__device__ __forceinline__ void mma16816(float* d, const uint32_t* a, const uint32_t* b) {
    asm volatile("mma.sync.aligned.m16n8k16.row.col.f32.f16.f16.f32 "
                 "{%0,%1,%2,%3}, {%4,%5,%6,%7}, {%8,%9}, {%0,%1,%2,%3};"
                 : "+f"(d[0]), "+f"(d[1]), "+f"(d[2]), "+f"(d[3])
                 : "r"(a[0]), "r"(a[1]), "r"(a[2]), "r"(a[3]), "r"(b[0]), "r"(b[1]));
}

// convert one float4 (4 consecutive k-values, 8 bytes of fp16) and store hi/lo
__device__ __forceinline__ void cvt_store_nb(char* smem, int row, int c4, float4 v) {
    __half h0 = __float2half_rn(v.x), h1 = __float2half_rn(v.y);
    __half h2 = __float2half_rn(v.z), h3 = __float2half_rn(v.w);
    __half l0 = __float2half_rn(v.x - __half2float(h0));
    __half l1 = __float2half_rn(v.y - __half2float(h1));
    __half l2 = __float2half_rn(v.z - __half2float(h2));
    __half l3 = __float2half_rn(v.w - __half2float(h3));
    uint2 hv, lv;
    hv.x = ((uint32_t)__half_as_ushort(h1) << 16) | __half_as_ushort(h0);
    hv.y = ((uint32_t)__half_as_ushort(h3) << 16) | __half_as_ushort(h2);
    lv.x = ((uint32_t)__half_as_ushort(l1) << 16) | __half_as_ushort(l0);
    lv.y = ((uint32_t)__half_as_ushort(l3) << 16) | __half_as_ushort(l2);
    uint32_t off = (uint32_t)row * PITCH_B + (uint32_t)c4 * 8;
    *reinterpret_cast<uint2*>(smem + SM_NB_HI + off) = hv;
    *reinterpret_cast<uint2*>(smem + SM_NB_LO + off) = lv;
}

__global__ void __launch_bounds__(THREADS, 1)
hete_agg_hmma3(const float* __restrict__ self_v,
               const float* __restrict__ nb_g,
               const float* __restrict__ w_g,
               const float* __restrict__ q_g,
               float* __restrict__ out,
               int B) {
    extern __shared__ char smem[];
    const uint32_t smb = smem_u32(smem);
    const int tid  = threadIdx.x;
    const int lane = tid & 31;
    const int wid  = tid >> 5;              // 0..15
    const int mbase = (wid >> 2) * 32;      // warp tile rows [mbase,+32)
    const int nbase = (wid & 3) * 32;       //           cols [nbase,+32)

    float* self_s  = reinterpret_cast<float*>(smem + SM_SELF);
    float* q_s     = reinterpret_cast<float*>(smem + SM_Q);
    float* msg_s   = reinterpret_cast<float*>(smem + SM_MSG);
    float* score_s = reinterpret_cast<float*>(smem + SM_SCORE);

    // ---- stage w^T hi/lo fp16 (once); q ----
    for (int idx = tid; idx < DDIM * DDIM; idx += THREADS) {
        int k = idx >> 7, e = idx & 127;
        float x = w_g[idx];
        __half h = __float2half_rn(x);
        __half l = __float2half_rn(x - __half2float(h));
        *reinterpret_cast<__half*>(smem + SM_W_HI + e * PITCH_B + k * 2) = h;
        *reinterpret_cast<__half*>(smem + SM_W_LO + e * PITCH_B + k * 2) = l;
    }
    if (tid < DDIM) q_s[tid] = q_g[tid];

    const int ngroups = (B + GB - 1) / GB;

    // ---- prologue: stage nb + self for first group (buf 0) ----
    int grp = blockIdx.x;
    if (grp < ngroups) {
        const int b0 = grp * GB;
        #pragma unroll
        for (int it = 0; it < 8; it++) {
            int unit = it * THREADS + tid;      // float4 index in 128x32
            int row = unit >> 5;
            int b = b0 + (row >> 5);
            int bc = (b < B) ? b : (B - 1);
            float4 v = *reinterpret_cast<const float4*>(
                nb_g + ((size_t)bc * NNBR + (row & 31)) * DDIM + (unit & 31) * 4);
            cvt_store_nb(smem, row, unit & 31, v);
        }
        {
            int b = b0 + (tid >> 7);
            int bc = (b < B) ? b : (B - 1);
            self_s[tid] = self_v[(size_t)bc * DDIM + (tid & 127)];
        }
    }

    int buf = 0;
    for (; grp < ngroups; grp += gridDim.x) {
        const int b0 = grp * GB;
        __syncthreads();                       // staged nb/self visible

        // ================= GEMM: fused 3-pass compensated =================
        float acc[2][4][4];
        #pragma unroll
        for (int mt = 0; mt < 2; mt++)
            #pragma unroll
            for (int nt = 0; nt < 4; nt++)
                #pragma unroll
                for (int j = 0; j < 4; j++) acc[mt][nt][j] = 0.f;

        const uint32_t a_off = (uint32_t)(mbase + (lane & 15)) * PITCH_B + ((lane >> 4) << 4);
        const uint32_t a_hi = smb + SM_NB_HI + a_off;
        const uint32_t a_lo = smb + SM_NB_LO + a_off;
        // B pair-load: lanes 0-7 rows n0-7/k0-7; 8-15 n0-7/k8-15; 16-23 n8-15/k0-7; 24-31 n8-15/k8-15
        const uint32_t b_off = (uint32_t)(nbase + ((lane >> 4) << 3) + (lane & 7)) * PITCH_B
                               + (((lane >> 3) & 1) << 4);
        const uint32_t b_hi = smb + SM_W_HI + b_off;
        const uint32_t b_lo = smb + SM_W_LO + b_off;

        #pragma unroll 2
        for (int ks = 0; ks < 8; ks++) {
            const uint32_t ka = ks * 32;
            uint32_t Ah[2][4], Al[2][4];
            ldsm_x4(Ah[0], a_hi + ka);
            ldsm_x4(Ah[1], a_hi + 16 * PITCH_B + ka);
            ldsm_x4(Al[0], a_lo + ka);
            ldsm_x4(Al[1], a_lo + 16 * PITCH_B + ka);
            uint32_t Bh[2][4], Bl[2][4];       // pair p covers n-tiles 2p, 2p+1
            #pragma unroll
            for (int p = 0; p < 2; p++) {
                ldsm_x4(Bh[p], b_hi + p * 16 * PITCH_B + ka);
                ldsm_x4(Bl[p], b_lo + p * 16 * PITCH_B + ka);
            }
            // pass 1: Ah*Bh
            #pragma unroll
            for (int p = 0; p < 2; p++)
                #pragma unroll
                for (int hf = 0; hf < 2; hf++)
                    #pragma unroll
                    for (int mt = 0; mt < 2; mt++)
                        mma16816(acc[mt][2 * p + hf], Ah[mt], &Bh[p][2 * hf]);
            // pass 2: Ah*Bl
            #pragma unroll
            for (int p = 0; p < 2; p++)
                #pragma unroll
                for (int hf = 0; hf < 2; hf++)
                    #pragma unroll
                    for (int mt = 0; mt < 2; mt++)
                        mma16816(acc[mt][2 * p + hf], Ah[mt], &Bl[p][2 * hf]);
            // pass 3: Al*Bh
            #pragma unroll
            for (int p = 0; p < 2; p++)
                #pragma unroll
                for (int hf = 0; hf < 2; hf++)
                    #pragma unroll
                    for (int mt = 0; mt < 2; mt++)
                        mma16816(acc[mt][2 * p + hf], Al[mt], &Bh[p][2 * hf]);
        }

        // ---- spill msg tile: msg[row][e] fp32 pitch 136 ----
        {
            const int r0 = mbase + (lane >> 2);
            const int c0 = nbase + 2 * (lane & 3);
            #pragma unroll
            for (int mt = 0; mt < 2; mt++)
                #pragma unroll
                for (int nt = 0; nt < 4; nt++) {
                    const float* d = acc[mt][nt];
                    const int r = r0 + mt * 16;
                    const int c = c0 + nt * 8;
                    *reinterpret_cast<float2*>(msg_s + r * MSG_PITCH + c) =
                        make_float2(d[0], d[1]);
                    *reinterpret_cast<float2*>(msg_s + (r + 8) * MSG_PITCH + c) =
                        make_float2(d[2], d[3]);
                }
        }

        // ---- prefetch next group's raw nb/self (latency overlaps barrier+epilogue) ----
        const int ngrp = grp + gridDim.x;
        const bool hasnext = (ngrp < ngroups);
        float4 raw[8];
        float selfraw;
        if (hasnext) {
            const int b0n = ngrp * GB;
            #pragma unroll
            for (int it = 0; it < 8; it++) {
                int unit = it * THREADS + tid;
                int row = unit >> 5;
                int b = b0n + (row >> 5);
                int bc = (b < B) ? b : (B - 1);
                raw[it] = *reinterpret_cast<const float4*>(
                    nb_g + ((size_t)bc * NNBR + (row & 31)) * DDIM + (unit & 31) * 4);
            }
            {
                int b = b0n + (tid >> 7);
                int bc = (b < B) ? b : (B - 1);
                selfraw = self_v[(size_t)bc * DDIM + (tid & 127)];
            }
        }
        __syncthreads();                       // msg visible

        // ================= epilogue: quarter (tid>>7) owns batch g =================
        const int g    = tid >> 7;
        const int htid = tid & 127;
        const int hw   = (tid >> 5) & 3;       // warp within quarter
        const float* selfb = self_s + buf * (GB * DDIM);

        {
            float sv[4], qv[4];
            #pragma unroll
            for (int c = 0; c < 4; c++) {
                sv[c] = selfb[g * DDIM + lane + 32 * c];
                qv[c] = q_s[lane + 32 * c];
            }
            // scores for neighbors n = hw*8 .. +7 (warp-reduce over e)
            #pragma unroll
            for (int j = 0; j < 8; j++) {
                const int n = hw * 8 + j;
                const float* mrow = msg_s + (g * 32 + n) * MSG_PITCH;
                float s = 0.f;
                #pragma unroll
                for (int c = 0; c < 4; c++) {
                    float x = sv[c] * mrow[lane + 32 * c];
                    x = (x >= 0.f) ? x : LRELU * x;
                    s = fmaf(x, qv[c], s);
                }
                #pragma unroll
                for (int o = 16; o; o >>= 1) s += __shfl_xor_sync(0xffffffffu, s, o);
                if (lane == 0) score_s[g * 32 + n] = s;
            }
            __syncthreads();

            // softmax over 32 neighbors (lane = n), redundant per warp
            float sc = score_s[g * 32 + lane];
            float mx = sc;
            #pragma unroll
            for (int o = 16; o; o >>= 1) mx = fmaxf(mx, __shfl_xor_sync(0xffffffffu, mx, o));
            float ex = expf(sc - mx);
            float ssum = ex;
            #pragma unroll
            for (int o = 16; o; o >>= 1) ssum += __shfl_xor_sync(0xffffffffu, ssum, o);
            const float alpha = ex / ssum;

            // out[e] = sum_n alpha_n * msg[n][e]
            const int e = htid;
            float o = 0.f;
            #pragma unroll
            for (int n = 0; n < 32; n++) {
                float a = __shfl_sync(0xffffffffu, alpha, n);
                o = fmaf(a, msg_s[(g * 32 + n) * MSG_PITCH + e], o);
            }
            const int b = b0 + g;
            if (b < B) out[(size_t)b * DDIM + e] = o;
        }

        // ---- commit prefetched nb/self for next group ----
        if (hasnext) {
            #pragma unroll
            for (int it = 0; it < 8; it++) {
                int unit = it * THREADS + tid;
                cvt_store_nb(smem, unit >> 5, unit & 31, raw[it]);
            }
            self_s[(buf ^ 1) * (GB * DDIM) + tid] = selfraw;
        }
        buf ^= 1;
    }
}

extern "C" void kernel_launch(void* const* d_in, const int* in_sizes, int n_in,
                              void* d_out, int out_size) {
    const float* self_v = (const float*)d_in[0];   // [B, 128]
    const float* nb_g   = (const float*)d_in[1];   // [B, 32, 128]
    const float* w_g    = (const float*)d_in[2];   // [128, 128]
    const float* q_g    = (const float*)d_in[3];   // [128, 1]
    float* out = (float*)d_out;

    const int B = in_sizes[0] / DDIM;
    const int ngroups = (B + GB - 1) / GB;

    cudaFuncSetAttribute(hete_agg_hmma3, cudaFuncAttributeMaxDynamicSharedMemorySize, SM_TOTAL);

    int dev = 0, nsm = 148;
    cudaGetDevice(&dev);
    cudaDeviceGetAttribute(&nsm, cudaDevAttrMultiProcessorCount, dev);
    int grid = (ngroups < nsm) ? ngroups : nsm;

    hete_agg_hmma3<<<grid, THREADS, SM_TOTAL>>>(self_v, nb_g, w_g, q_g, out, B);
}

// round 7
// speedup vs baseline: 5.2984x; 1.4963x over previous
#include <cuda_runtime.h>
#include <cuda_fp16.h>
#include <cstdint>

#define THREADS 512
#define DDIM    128
#define NNBR    32
#define GB      4                 // batches per group -> 128 GEMM rows
#define LRELU   0.2f

#define PITCH_B   272             // bytes/row of fp16 tiles (17*16B -> ldsm conflict-free)
#define MSG_PITCH 136             // floats/row of msg

// ---------------- SMEM layout (bytes) ----------------
#define SM_W_HI   0                                // w^T hi, 128 x 272B
#define SM_W_LO   (SM_W_HI  + 128 * PITCH_B)       // 34816
#define SM_NB     (SM_W_LO  + 128 * PITCH_B)       // 69632  nb fp16 (single precision level)
#define SM_MSG    (SM_NB    + 128 * PITCH_B)       // 104448 msg fp32 128 x 136
#define SM_SELF   (SM_MSG   + 128 * MSG_PITCH * 4) // 174080 self [2 buf][4][128] fp32
#define SM_Q      (SM_SELF  + 2 * GB * DDIM * 4)   // 178176
#define SM_SCORE  (SM_Q     + 512)                 // 178688 scores [4 g][32]
#define SM_PART   (SM_SCORE + 512)                 // 179200 partial out [4 g][4 hw][128]
#define SM_TOTAL  (SM_PART  + 8192)                // 187392 B (~183 KB)

__device__ __forceinline__ uint32_t smem_u32(const void* p) {
    uint32_t a;
    asm("{ .reg .u64 t; cvta.to.shared.u64 t, %1; cvt.u32.u64 %0, t; }" : "=r"(a) : "l"(p));
    return a;
}
__device__ __forceinline__ void ldsm_x4(uint32_t* r, uint32_t addr) {
    asm volatile("ldmatrix.sync.aligned.m8n8.x4.shared.b16 {%0,%1,%2,%3}, [%4];"
                 : "=r"(r[0]), "=r"(r[1]), "=r"(r[2]), "=r"(r[3]) : "r"(addr));
}
__device__ __forceinline__ void mma16816(float* d, const uint32_t* a, const uint32_t* b) {
    asm volatile("mma.sync.aligned.m16n8k16.row.col.f32.f16.f16.f32 "
                 "{%0,%1,%2,%3}, {%4,%5,%6,%7}, {%8,%9}, {%0,%1,%2,%3};"
                 : "+f"(d[0]), "+f"(d[1]), "+f"(d[2]), "+f"(d[3])
                 : "r"(a[0]), "r"(a[1]), "r"(a[2]), "r"(a[3]), "r"(b[0]), "r"(b[1]));
}
#define QBAR(g) asm volatile("bar.sync %0, 128;" :: "r"((g) + 1) : "memory")

// convert one float4 (4 consecutive k-values) to fp16 and store (8 bytes)
__device__ __forceinline__ void cvt_store_nb(char* smem, int row, int c4, float4 v) {
    __half h0 = __float2half_rn(v.x), h1 = __float2half_rn(v.y);
    __half h2 = __float2half_rn(v.z), h3 = __float2half_rn(v.w);
    uint2 hv;
    hv.x = ((uint32_t)__half_as_ushort(h1) << 16) | __half_as_ushort(h0);
    hv.y = ((uint32_t)__half_as_ushort(h3) << 16) | __half_as_ushort(h2);
    *reinterpret_cast<uint2*>(smem + SM_NB + (uint32_t)row * PITCH_B + (uint32_t)c4 * 8) = hv;
}

__global__ void __launch_bounds__(THREADS, 1)
hete_agg_hmma4(const float* __restrict__ self_v,
               const float* __restrict__ nb_g,
               const float* __restrict__ w_g,
               const float* __restrict__ q_g,
               float* __restrict__ out,
               int B) {
    extern __shared__ char smem[];
    const uint32_t smb = smem_u32(smem);
    const int tid  = threadIdx.x;
    const int lane = tid & 31;
    const int wid  = tid >> 5;              // 0..15
    const int mbase = (wid >> 2) * 32;      // warp tile rows [mbase,+32)
    const int nbase = (wid & 3) * 32;       //           cols [nbase,+32)

    float* self_s  = reinterpret_cast<float*>(smem + SM_SELF);
    float* q_s     = reinterpret_cast<float*>(smem + SM_Q);
    float* msg_s   = reinterpret_cast<float*>(smem + SM_MSG);
    float* score_s = reinterpret_cast<float*>(smem + SM_SCORE);
    float* part_s  = reinterpret_cast<float*>(smem + SM_PART);

    // ---- stage w^T hi/lo fp16 (once); q ----
    for (int idx = tid; idx < DDIM * DDIM; idx += THREADS) {
        int k = idx >> 7, e = idx & 127;
        float x = w_g[idx];
        __half h = __float2half_rn(x);
        __half l = __float2half_rn(x - __half2float(h));
        *reinterpret_cast<__half*>(smem + SM_W_HI + e * PITCH_B + k * 2) = h;
        *reinterpret_cast<__half*>(smem + SM_W_LO + e * PITCH_B + k * 2) = l;
    }
    if (tid < DDIM) q_s[tid] = q_g[tid];

    const int ngroups = (B + GB - 1) / GB;

    // ---- prologue: stage nb + self for first group (buf 0) ----
    int grp = blockIdx.x;
    if (grp < ngroups) {
        const int b0 = grp * GB;
        #pragma unroll
        for (int it = 0; it < 8; it++) {
            int unit = it * THREADS + tid;      // float4 index in 128x32
            int row = unit >> 5;
            int b = b0 + (row >> 5);
            int bc = (b < B) ? b : (B - 1);
            float4 v = *reinterpret_cast<const float4*>(
                nb_g + ((size_t)bc * NNBR + (row & 31)) * DDIM + (unit & 31) * 4);
            cvt_store_nb(smem, row, unit & 31, v);
        }
        {
            int b = b0 + (tid >> 7);
            int bc = (b < B) ? b : (B - 1);
            self_s[tid] = self_v[(size_t)bc * DDIM + (tid & 127)];
        }
    }

    int buf = 0;
    for (; grp < ngroups; grp += gridDim.x) {
        const int b0 = grp * GB;
        __syncthreads();                       // staged nb/self visible

        // ========== GEMM: msg = nb_f16 @ (w_hi + w_lo), 2-pass compensated ==========
        float acc[2][4][4];
        #pragma unroll
        for (int mt = 0; mt < 2; mt++)
            #pragma unroll
            for (int nt = 0; nt < 4; nt++)
                #pragma unroll
                for (int j = 0; j < 4; j++) acc[mt][nt][j] = 0.f;

        const uint32_t a_ptr = smb + SM_NB
            + (uint32_t)(mbase + (lane & 15)) * PITCH_B + ((lane >> 4) << 4);
        // B pair-load: lanes 0-7 rows n0-7/k0-7; 8-15 n0-7/k8-15; 16-23 n8-15/k0-7; 24-31 n8-15/k8-15
        const uint32_t b_off = (uint32_t)(nbase + ((lane >> 4) << 3) + (lane & 7)) * PITCH_B
                               + (((lane >> 3) & 1) << 4);
        const uint32_t b_hi = smb + SM_W_HI + b_off;
        const uint32_t b_lo = smb + SM_W_LO + b_off;

        #pragma unroll 2
        for (int ks = 0; ks < 8; ks++) {
            const uint32_t ka = ks * 32;
            uint32_t Ar[2][4];
            ldsm_x4(Ar[0], a_ptr + ka);
            ldsm_x4(Ar[1], a_ptr + 16 * PITCH_B + ka);
            uint32_t Bh[2][4], Bl[2][4];       // pair p covers n-tiles 2p, 2p+1
            #pragma unroll
            for (int p = 0; p < 2; p++) {
                ldsm_x4(Bh[p], b_hi + p * 16 * PITCH_B + ka);
                ldsm_x4(Bl[p], b_lo + p * 16 * PITCH_B + ka);
            }
            // pass 1: A * w_hi
            #pragma unroll
            for (int p = 0; p < 2; p++)
                #pragma unroll
                for (int hf = 0; hf < 2; hf++)
                    #pragma unroll
                    for (int mt = 0; mt < 2; mt++)
                        mma16816(acc[mt][2 * p + hf], Ar[mt], &Bh[p][2 * hf]);
            // pass 2: A * w_lo
            #pragma unroll
            for (int p = 0; p < 2; p++)
                #pragma unroll
                for (int hf = 0; hf < 2; hf++)
                    #pragma unroll
                    for (int mt = 0; mt < 2; mt++)
                        mma16816(acc[mt][2 * p + hf], Ar[mt], &Bl[p][2 * hf]);
        }

        // ---- spill msg tile: msg[row][e] fp32 pitch 136 ----
        {
            const int r0 = mbase + (lane >> 2);
            const int c0 = nbase + 2 * (lane & 3);
            #pragma unroll
            for (int mt = 0; mt < 2; mt++)
                #pragma unroll
                for (int nt = 0; nt < 4; nt++) {
                    const float* d = acc[mt][nt];
                    const int r = r0 + mt * 16;
                    const int c = c0 + nt * 8;
                    *reinterpret_cast<float2*>(msg_s + r * MSG_PITCH + c) =
                        make_float2(d[0], d[1]);
                    *reinterpret_cast<float2*>(msg_s + (r + 8) * MSG_PITCH + c) =
                        make_float2(d[2], d[3]);
                }
        }

        // ---- prefetch next group's raw nb/self (LDG latency overlaps epilogue) ----
        const int ngrp = grp + gridDim.x;
        const bool hasnext = (ngrp < ngroups);
        float4 raw[8];
        float selfraw;
        if (hasnext) {
            const int b0n = ngrp * GB;
            #pragma unroll
            for (int it = 0; it < 8; it++) {
                int unit = it * THREADS + tid;
                int row = unit >> 5;
                int b = b0n + (row >> 5);
                int bc = (b < B) ? b : (B - 1);
                raw[it] = *reinterpret_cast<const float4*>(
                    nb_g + ((size_t)bc * NNBR + (row & 31)) * DDIM + (unit & 31) * 4);
            }
            {
                int b = b0n + (tid >> 7);
                int bc = (b < B) ? b : (B - 1);
                selfraw = self_v[(size_t)bc * DDIM + (tid & 127)];
            }
        }
        __syncthreads();                       // msg visible; nb free for restaging

        // ========== fused epilogue: quarter (tid>>7) owns batch g ==========
        const int g    = tid >> 7;
        const int htid = tid & 127;
        const int hw   = (tid >> 5) & 3;       // warp within quarter
        const float* selfb = self_s + buf * (GB * DDIM);

        {
            float sv[4], qv[4];
            #pragma unroll
            for (int c = 0; c < 4; c++) {
                sv[c] = selfb[g * DDIM + lane + 32 * c];
                qv[c] = q_s[lane + 32 * c];
            }
            // read msg once: this thread holds msg[n = hw*8+j][e = lane+32c]
            float m[8][4];
            #pragma unroll
            for (int j = 0; j < 8; j++) {
                const float* mrow = msg_s + (g * 32 + hw * 8 + j) * MSG_PITCH;
                #pragma unroll
                for (int c = 0; c < 4; c++) m[j][c] = mrow[lane + 32 * c];
            }
            // scores for this warp's 8 neighbors (reduce over e within warp)
            #pragma unroll
            for (int j = 0; j < 8; j++) {
                float s = 0.f;
                #pragma unroll
                for (int c = 0; c < 4; c++) {
                    float x = sv[c] * m[j][c];
                    x = (x >= 0.f) ? x : LRELU * x;
                    s = fmaf(x, qv[c], s);
                }
                #pragma unroll
                for (int o = 16; o; o >>= 1) s += __shfl_xor_sync(0xffffffffu, s, o);
                if (lane == 0) score_s[g * 32 + hw * 8 + j] = s;
            }
            QBAR(g);

            // softmax over 32 neighbors (lane = n), redundant per warp in quarter
            float sc = score_s[g * 32 + lane];
            float mx = sc;
            #pragma unroll
            for (int o = 16; o; o >>= 1) mx = fmaxf(mx, __shfl_xor_sync(0xffffffffu, mx, o));
            float ex = expf(sc - mx);
            float ssum = ex;
            #pragma unroll
            for (int o = 16; o; o >>= 1) ssum += __shfl_xor_sync(0xffffffffu, ssum, o);
            const float alpha = ex / ssum;

            // weighted partials from registers: pe[c] = sum_{j} alpha_{hw*8+j} * m[j][c]
            float pe[4] = {0.f, 0.f, 0.f, 0.f};
            #pragma unroll
            for (int j = 0; j < 8; j++) {
                float a = __shfl_sync(0xffffffffu, alpha, hw * 8 + j);
                #pragma unroll
                for (int c = 0; c < 4; c++) pe[c] = fmaf(a, m[j][c], pe[c]);
            }
            float* pp = part_s + (g * 4 + hw) * DDIM;
            #pragma unroll
            for (int c = 0; c < 4; c++) pp[lane + 32 * c] = pe[c];
            QBAR(g);

            // combine across the quarter's 4 warps; thread htid owns e = htid
            const float* pb = part_s + g * 4 * DDIM;
            float o = pb[htid] + pb[DDIM + htid] + pb[2 * DDIM + htid] + pb[3 * DDIM + htid];
            const int b = b0 + g;
            if (b < B) out[(size_t)b * DDIM + htid] = o;
        }

        // ---- commit prefetched nb/self for next group (no barrier needed:
        //      all GEMM reads of nb finished before the msg __syncthreads) ----
        if (hasnext) {
            #pragma unroll
            for (int it = 0; it < 8; it++) {
                int unit = it * THREADS + tid;
                cvt_store_nb(smem, unit >> 5, unit & 31, raw[it]);
            }
            self_s[(buf ^ 1) * (GB * DDIM) + tid] = selfraw;
        }
        buf ^= 1;
    }
}

extern "C" void kernel_launch(void* const* d_in, const int* in_sizes, int n_in,
                              void* d_out, int out_size) {
    const float* self_v = (const float*)d_in[0];   // [B, 128]
    const float* nb_g   = (const float*)d_in[1];   // [B, 32, 128]
    const float* w_g    = (const float*)d_in[2];   // [128, 128]
    const float* q_g    = (const float*)d_in[3];   // [128, 1]
    float* out = (float*)d_out;

    const int B = in_sizes[0] / DDIM;
    const int ngroups = (B + GB - 1) / GB;

    cudaFuncSetAttribute(hete_agg_hmma4, cudaFuncAttributeMaxDynamicSharedMemorySize, SM_TOTAL);

    int dev = 0, nsm = 148;
    cudaGetDevice(&dev);
    cudaDeviceGetAttribute(&nsm, cudaDevAttrMultiProcessorCount, dev);
    int grid = (ngroups < nsm) ? ngroups : nsm;

    hete_agg_hmma4<<<grid, THREADS, SM_TOTAL>>>(self_v, nb_g, w_g, q_g, out, B);
}

// round 8
// speedup vs baseline: 7.4914x; 1.4139x over previous
#include <cuda_runtime.h>
#include <cuda_fp16.h>
#include <cstdint>

#define THREADS 512
#define DDIM    128
#define NNBR    32
#define GB      4                 // batches per group -> 128 GEMM rows
#define LRELU   0.2f

#define PITCH_B 272               // bytes/row of fp16 tiles (17*16B -> ldsm conflict-free)

// ---------------- SMEM layout (bytes) ----------------
#define SM_W      0                          // w^T fp16, 128 x 272B = 34816
#define SM_NB0    34816                      // nb fp16 buffer 0 (34816)
#define SM_NB1    69632                      // nb fp16 buffer 1 (34816)
#define SM_SELF   104448                     // self [2 buf][4][128] fp32 = 4096
#define SM_Q      108544                     // 128 fp32 = 512
#define SM_PART   109056                     // score partials [4 g][4 nw][32] fp32 = 2048
#define SM_TOTAL  111104                     // ~108.5 KB

__device__ __forceinline__ uint32_t smem_u32(const void* p) {
    uint32_t a;
    asm("{ .reg .u64 t; cvta.to.shared.u64 t, %1; cvt.u32.u64 %0, t; }" : "=r"(a) : "l"(p));
    return a;
}
__device__ __forceinline__ void ldsm_x4(uint32_t* r, uint32_t addr) {
    asm volatile("ldmatrix.sync.aligned.m8n8.x4.shared.b16 {%0,%1,%2,%3}, [%4];"
                 : "=r"(r[0]), "=r"(r[1]), "=r"(r[2]), "=r"(r[3]) : "r"(addr));
}
__device__ __forceinline__ void mma16816(float* d, const uint32_t* a, const uint32_t* b) {
    asm volatile("mma.sync.aligned.m16n8k16.row.col.f32.f16.f16.f32 "
                 "{%0,%1,%2,%3}, {%4,%5,%6,%7}, {%8,%9}, {%0,%1,%2,%3};"
                 : "+f"(d[0]), "+f"(d[1]), "+f"(d[2]), "+f"(d[3])
                 : "r"(a[0]), "r"(a[1]), "r"(a[2]), "r"(a[3]), "r"(b[0]), "r"(b[1]));
}
#define QBAR(g) asm volatile("bar.sync %0, 128;" :: "r"((g) + 1) : "memory")

// convert one float4 (4 consecutive k-values) to fp16 and store (8 bytes)
__device__ __forceinline__ void cvt_store_nb(char* smem, uint32_t nb_base, int row, int c4, float4 v) {
    __half h0 = __float2half_rn(v.x), h1 = __float2half_rn(v.y);
    __half h2 = __float2half_rn(v.z), h3 = __float2half_rn(v.w);
    uint2 hv;
    hv.x = ((uint32_t)__half_as_ushort(h1) << 16) | __half_as_ushort(h0);
    hv.y = ((uint32_t)__half_as_ushort(h3) << 16) | __half_as_ushort(h2);
    *reinterpret_cast<uint2*>(smem + nb_base + (uint32_t)row * PITCH_B + (uint32_t)c4 * 8) = hv;
}

__global__ void __launch_bounds__(THREADS, 1)
hete_agg_hmma5(const float* __restrict__ self_v,
               const float* __restrict__ nb_g,
               const float* __restrict__ w_g,
               const float* __restrict__ q_g,
               float* __restrict__ out,
               int B) {
    extern __shared__ char smem[];
    const uint32_t smb = smem_u32(smem);
    const int tid  = threadIdx.x;
    const int lane = tid & 31;
    const int wid  = tid >> 5;              // 0..15
    const int g    = wid >> 2;              // batch within group (rows g*32..+31)
    const int nw   = wid & 3;               // e-slice
    const int mbase = g * 32;
    const int nbase = nw * 32;

    float* self_s = reinterpret_cast<float*>(smem + SM_SELF);
    float* q_s    = reinterpret_cast<float*>(smem + SM_Q);
    float* part_s = reinterpret_cast<float*>(smem + SM_PART);

    // ---- stage w^T fp16 (single precision level; once); q ----
    for (int idx = tid; idx < DDIM * DDIM; idx += THREADS) {
        int k = idx >> 7, e = idx & 127;
        *reinterpret_cast<__half*>(smem + SM_W + e * PITCH_B + k * 2) =
            __float2half_rn(w_g[idx]);
    }
    if (tid < DDIM) q_s[tid] = q_g[tid];

    const int ngroups = (B + GB - 1) / GB;

    // ---- prologue: stage nb + self for first group (buf 0) ----
    int grp = blockIdx.x;
    if (grp < ngroups) {
        const int b0 = grp * GB;
        #pragma unroll
        for (int it = 0; it < 8; it++) {
            int unit = it * THREADS + tid;      // float4 index in 128x32
            int row = unit >> 5;
            int b = b0 + (row >> 5);
            int bc = (b < B) ? b : (B - 1);
            float4 v = *reinterpret_cast<const float4*>(
                nb_g + ((size_t)bc * NNBR + (row & 31)) * DDIM + (unit & 31) * 4);
            cvt_store_nb(smem, SM_NB0, row, unit & 31, v);
        }
        {
            int b = b0 + (tid >> 7);
            int bc = (b < B) ? b : (B - 1);
            self_s[tid] = self_v[(size_t)bc * DDIM + (tid & 127)];
        }
    }

    int buf = 0;
    for (; grp < ngroups; grp += gridDim.x) {
        const int b0 = grp * GB;
        __syncthreads();        // staged nb[buf]/self[buf] visible; part_s reusable

        // ========== GEMM (single pass, w pre-rounded): acc = nb_f16 @ w_f16^T ==========
        float acc[2][4][4];
        #pragma unroll
        for (int mt = 0; mt < 2; mt++)
            #pragma unroll
            for (int nt = 0; nt < 4; nt++)
                #pragma unroll
                for (int j = 0; j < 4; j++) acc[mt][nt][j] = 0.f;

        const uint32_t nb_base = buf ? SM_NB1 : SM_NB0;
        const uint32_t a_ptr = smb + nb_base
            + (uint32_t)(mbase + (lane & 15)) * PITCH_B + ((lane >> 4) << 4);
        // B pair-load: lanes 0-7 rows n0-7/k0-7; 8-15 n0-7/k8-15; 16-23 n8-15/k0-7; 24-31 n8-15/k8-15
        const uint32_t b_ptr = smb + SM_W
            + (uint32_t)(nbase + ((lane >> 4) << 3) + (lane & 7)) * PITCH_B
            + (((lane >> 3) & 1) << 4);

        #pragma unroll
        for (int ks = 0; ks < 8; ks++) {
            const uint32_t ka = ks * 32;
            uint32_t Ar[2][4], Bp[2][4];
            ldsm_x4(Ar[0], a_ptr + ka);
            ldsm_x4(Ar[1], a_ptr + 16 * PITCH_B + ka);
            ldsm_x4(Bp[0], b_ptr + ka);
            ldsm_x4(Bp[1], b_ptr + 16 * PITCH_B + ka);
            #pragma unroll
            for (int p = 0; p < 2; p++)
                #pragma unroll
                for (int hf = 0; hf < 2; hf++)
                    #pragma unroll
                    for (int mt = 0; mt < 2; mt++)
                        mma16816(acc[mt][2 * p + hf], Ar[mt], &Bp[p][2 * hf]);
        }

        // ---- prefetch next group's raw nb/self (LDG latency overlaps epilogue) ----
        const int ngrp = grp + gridDim.x;
        const bool hasnext = (ngrp < ngroups);
        float4 raw[8];
        float selfraw;
        if (hasnext) {
            const int b0n = ngrp * GB;
            #pragma unroll
            for (int it = 0; it < 8; it++) {
                int unit = it * THREADS + tid;
                int row = unit >> 5;
                int b = b0n + (row >> 5);
                int bc = (b < B) ? b : (B - 1);
                raw[it] = *reinterpret_cast<const float4*>(
                    nb_g + ((size_t)bc * NNBR + (row & 31)) * DDIM + (unit & 31) * 4);
            }
            {
                int b = b0n + (tid >> 7);
                int bc = (b < B) ? b : (B - 1);
                selfraw = self_v[(size_t)bc * DDIM + (tid & 127)];
            }
        }

        // ========== register-resident epilogue ==========
        // thread owns: rows n = mt*16 + 8h + (lane>>2); cols e = nbase + nt*8 + 2(lane&3)+cc
        {
            const float* selfb = self_s + buf * (GB * DDIM) + g * DDIM;
            float sv[4][2], qv[4][2];
            #pragma unroll
            for (int nt = 0; nt < 4; nt++)
                #pragma unroll
                for (int cc = 0; cc < 2; cc++) {
                    int e = nbase + nt * 8 + 2 * (lane & 3) + cc;
                    sv[nt][cc] = selfb[e];
                    qv[nt][cc] = q_s[e];
                }

            // per-thread score partials for 4 rows (mt,h) over its 8 e's
            float s[2][2];
            #pragma unroll
            for (int mt = 0; mt < 2; mt++)
                #pragma unroll
                for (int h = 0; h < 2; h++) {
                    float acc_s = 0.f;
                    #pragma unroll
                    for (int nt = 0; nt < 4; nt++)
                        #pragma unroll
                        for (int cc = 0; cc < 2; cc++) {
                            float x = sv[nt][cc] * acc[mt][nt][2 * h + cc];
                            x = (x >= 0.f) ? x : LRELU * x;
                            acc_s = fmaf(x, qv[nt][cc], acc_s);
                        }
                    s[mt][h] = acc_s;
                }
            // reduce across lanes sharing a row (lane&3 varies): xor 1, 2
            #pragma unroll
            for (int mt = 0; mt < 2; mt++)
                #pragma unroll
                for (int h = 0; h < 2; h++) {
                    s[mt][h] += __shfl_xor_sync(0xffffffffu, s[mt][h], 1);
                    s[mt][h] += __shfl_xor_sync(0xffffffffu, s[mt][h], 2);
                }
            if ((lane & 3) == 0) {
                float* pp = part_s + (g * 4 + nw) * 32;
                #pragma unroll
                for (int mt = 0; mt < 2; mt++)
                    #pragma unroll
                    for (int h = 0; h < 2; h++)
                        pp[mt * 16 + 8 * h + (lane >> 2)] = s[mt][h];
            }
            QBAR(g);

            // full score (lane = n), softmax over 32 neighbors
            const float* pg = part_s + g * 4 * 32;
            float sc = pg[lane] + pg[32 + lane] + pg[64 + lane] + pg[96 + lane];
            float mx = sc;
            #pragma unroll
            for (int o = 16; o; o >>= 1) mx = fmaxf(mx, __shfl_xor_sync(0xffffffffu, mx, o));
            float ex = expf(sc - mx);
            float ssum = ex;
            #pragma unroll
            for (int o = 16; o; o >>= 1) ssum += __shfl_xor_sync(0xffffffffu, ssum, o);
            const float alpha = ex / ssum;

            // weighted sum: pe[nt][cc] = sum_{mt,h} alpha_row * m
            float ar[2][2];
            #pragma unroll
            for (int mt = 0; mt < 2; mt++)
                #pragma unroll
                for (int h = 0; h < 2; h++)
                    ar[mt][h] = __shfl_sync(0xffffffffu, alpha, mt * 16 + 8 * h + (lane >> 2));
            float pe[4][2];
            #pragma unroll
            for (int nt = 0; nt < 4; nt++)
                #pragma unroll
                for (int cc = 0; cc < 2; cc++) {
                    float v = 0.f;
                    #pragma unroll
                    for (int mt = 0; mt < 2; mt++)
                        #pragma unroll
                        for (int h = 0; h < 2; h++)
                            v = fmaf(ar[mt][h], acc[mt][nt][2 * h + cc], v);
                    pe[nt][cc] = v;
                }
            // reduce across lanes sharing cols (lane>>2 varies): xor 4, 8, 16
            #pragma unroll
            for (int nt = 0; nt < 4; nt++)
                #pragma unroll
                for (int cc = 0; cc < 2; cc++) {
                    #pragma unroll
                    for (int o = 4; o <= 16; o <<= 1)
                        pe[nt][cc] += __shfl_xor_sync(0xffffffffu, pe[nt][cc], o);
                }
            // lanes 0..3 write final out for e = nbase + nt*8 + 2*lane + cc
            const int b = b0 + g;
            if (lane < 4 && b < B) {
                float* ob = out + (size_t)b * DDIM + nbase + 2 * lane;
                #pragma unroll
                for (int nt = 0; nt < 4; nt++)
                    *reinterpret_cast<float2*>(ob + nt * 8) = make_float2(pe[nt][0], pe[nt][1]);
            }
        }

        // ---- commit prefetched nb/self into the other buffer ----
        if (hasnext) {
            const uint32_t nb_next = buf ? SM_NB0 : SM_NB1;
            #pragma unroll
            for (int it = 0; it < 8; it++) {
                int unit = it * THREADS + tid;
                cvt_store_nb(smem, nb_next, unit >> 5, unit & 31, raw[it]);
            }
            self_s[(buf ^ 1) * (GB * DDIM) + tid] = selfraw;
        }
        buf ^= 1;
    }
}

extern "C" void kernel_launch(void* const* d_in, const int* in_sizes, int n_in,
                              void* d_out, int out_size) {
    const float* self_v = (const float*)d_in[0];   // [B, 128]
    const float* nb_g   = (const float*)d_in[1];   // [B, 32, 128]
    const float* w_g    = (const float*)d_in[2];   // [128, 128]
    const float* q_g    = (const float*)d_in[3];   // [128, 1]
    float* out = (float*)d_out;

    const int B = in_sizes[0] / DDIM;
    const int ngroups = (B + GB - 1) / GB;

    cudaFuncSetAttribute(hete_agg_hmma5, cudaFuncAttributeMaxDynamicSharedMemorySize, SM_TOTAL);

    int dev = 0, nsm = 148;
    cudaGetDevice(&dev);
    cudaDeviceGetAttribute(&nsm, cudaDevAttrMultiProcessorCount, dev);
    int grid = (ngroups < nsm) ? ngroups : nsm;

    hete_agg_hmma5<<<grid, THREADS, SM_TOTAL>>>(self_v, nb_g, w_g, q_g, out, B);
}